// round 1
// baseline (speedup 1.0000x reference)
#include <cuda_runtime.h>

#define BATCH 2
#define CH 64
#define HH 224
#define WW 224
#define HW (HH*WW)           // 50176
#define NPIX (BATCH*HW)      // 100352
#define NOFF 18
#define KK 576               // 64*9

// ---------------- scratch (static device memory; no allocations) ----------------
__device__ float g_xh[NPIX*CH];      // NHWC input of current stage
__device__ float g_off[NPIX*NOFF];   // offsets NHWC
__device__ float g_yraw[NPIX*CH];    // pre-BN conv output NHWC
__device__ float g_y1n[NPIX*CH];     // stage-1 normalized output NHWC
__device__ float g_Wt[CH*KK];        // W transposed: Wt[k*64+o] = w_conv[o][k]
__device__ float g_sp[256*CH];       // partial sums
__device__ float g_qp[256*CH];       // partial sumsq
__device__ float g_ab[2*CH];         // per-channel scale a, shift b

// ---------------- NCHW -> NHWC transpose ----------------
__global__ __launch_bounds__(256) void k_nchw2nhwc(const float* __restrict__ x) {
    __shared__ float tile[32][33];
    int b = blockIdx.z;
    int s0 = blockIdx.x * 32, c0 = blockIdx.y * 32;
    int tx = threadIdx.x, ty = threadIdx.y;
#pragma unroll
    for (int j = 0; j < 4; j++) {
        int c = c0 + ty + j*8;
        tile[ty + j*8][tx] = x[(b*CH + c)*HW + s0 + tx];
    }
    __syncthreads();
#pragma unroll
    for (int j = 0; j < 4; j++) {
        int s = s0 + ty + j*8;
        g_xh[(b*HW + s)*CH + c0 + tx] = tile[tx][ty + j*8];
    }
}

// ---------------- transpose conv weights: Wt[k*64+o] = w[o*576+k] ----------------
__global__ void k_prepwt(const float* __restrict__ wconv) {
    int j = blockIdx.x * 256 + threadIdx.x;
    if (j < CH*KK) {
        int o = j & 63;
        int k = j >> 6;
        g_Wt[j] = wconv[o*KK + k];
    }
}

// ---------------- offset conv: 3x3, pad 1, 64->18 channels ----------------
// grid (4, 224, 2), block 160. smem: Wsm[18*576] + patch[c][3][68]
#define OFF_SMEM ((10376 + 64*204) * 4)
__global__ __launch_bounds__(160) void k_offconv(const float* __restrict__ in,
                                                 const float* __restrict__ woff,
                                                 const float* __restrict__ boff) {
    extern __shared__ float sm[];
    float* Ws = sm;              // 10368 floats
    float* patch = sm + 10376;   // 64*204 floats  ([c][kx(3)][p(68 padded, 66 used)])
    int t = threadIdx.x;
    int w0 = blockIdx.x * 64, h = blockIdx.y, b = blockIdx.z;

    for (int j = t; j < NOFF*KK; j += 160) Ws[j] = woff[j];
    for (int j = t; j < 3*66*64; j += 160) {
        int c = j & 63; int r = j >> 6; int p = r % 66; int kx = r / 66;
        int hr = h - 1 + kx; int wc = w0 - 1 + p;
        float v = 0.f;
        if ((unsigned)hr < (unsigned)HH && (unsigned)wc < (unsigned)WW)
            v = in[((b*HH + hr)*WW + wc)*CH + c];
        patch[c*204 + kx*68 + p] = v;
    }
    __syncthreads();

    if (t < 144) {
        int og = t >> 4;      // 0..8
        int pl = t & 15;      // 4 pixels each -> covers 64
        float acc0[4] = {0,0,0,0};
        float acc1[4] = {0,0,0,0};
        for (int c = 0; c < CH; c++) {
#pragma unroll
            for (int kx = 0; kx < 3; kx++) {
                const float* pr = patch + c*204 + kx*68 + pl*4;
                float4 f4 = *(const float4*)pr;
                float2 f2 = *(const float2*)(pr + 4);
                float pv[6] = {f4.x, f4.y, f4.z, f4.w, f2.x, f2.y};
                const float* wb0 = Ws + og*KK + c*9 + kx*3;
                const float* wb1 = Ws + (og+9)*KK + c*9 + kx*3;
#pragma unroll
                for (int ky = 0; ky < 3; ky++) {
                    float wa = wb0[ky], wb = wb1[ky];
#pragma unroll
                    for (int pp = 0; pp < 4; pp++) {
                        acc0[pp] = fmaf(wa, pv[ky+pp], acc0[pp]);
                        acc1[pp] = fmaf(wb, pv[ky+pp], acc1[pp]);
                    }
                }
            }
        }
        float bi0 = boff[og], bi1 = boff[og+9];
#pragma unroll
        for (int pp = 0; pp < 4; pp++) {
            int w = w0 + pl*4 + pp;
            if (w < WW) {
                int base = ((b*HH + h)*WW + w)*NOFF;
                g_off[base + og]     = acc0[pp] + bi0;
                g_off[base + og + 9] = acc1[pp] + bi1;
            }
        }
    }
}

// ---------------- deformable gather + 64x576 GEMM ----------------
// grid NPIX/32 blocks, 128 threads. smem: xoff[576][36] + 288 descriptors
#define DEF_SMEM ((20736 + 1152 + 1152) * 4)
__global__ __launch_bounds__(128) void k_deform(const float* __restrict__ in,
                                                float* __restrict__ yout) {
    extern __shared__ float sm[];
    float* xoff = sm;                                  // 576*36
    int4*   gA  = (int4*)(sm + 20736);                 // 288
    float4* gW  = (float4*)(sm + 20736 + 1152);        // 288
    int t = threadIdx.x;
    int pix0 = blockIdx.x * 32;
    int b = pix0 / HW; int hw = pix0 - b*HW;
    int h = hw / WW;  int w0 = hw - h*WW;

    // Phase A1: per (pixel, point) descriptors: 4 corner addresses + 4 bilinear weights
    for (int j = t; j < 288; j += 128) {
        int p = j / 9; int i = j - p*9;
        int pix = pix0 + p;
        float ox = g_off[pix*NOFF + i];
        float oy = g_off[pix*NOFF + 9 + i];
        float px = (float)(h + (i/3)) + ox;            // (h+1) + (i/3 - 1)
        float py = (float)(w0 + p + (i%3)) + oy;       // (w+1) + (i%3 - 1)
        float fx = floorf(px), fy = floorf(py);
        int x0 = (int)fx, y0 = (int)fy;
        int x1 = x0 + 1, y1 = y0 + 1;
        x0 = min(max(x0, 0), HH-1); x1 = min(max(x1, 0), HH-1);
        y0 = min(max(y0, 0), WW-1); y1 = min(max(y1, 0), WW-1);
        float pxc = fminf(fmaxf(px, 0.f), (float)(HH-1));
        float pyc = fminf(fmaxf(py, 0.f), (float)(WW-1));
        float wx0 = 1.f + (float)x0 - pxc;
        float wx1 = 1.f - (float)x1 + pxc;
        float wy0 = 1.f + (float)y0 - pyc;
        float wy1 = 1.f - (float)y1 + pyc;
        int base = b * HW;
        gA[j] = make_int4((base + x0*WW + y0)*CH, (base + x1*WW + y1)*CH,
                          (base + x0*WW + y1)*CH, (base + x1*WW + y0)*CH);
        gW[j] = make_float4(wx0*wy0, wx1*wy1, wx0*wy1, wx1*wy0);
    }
    __syncthreads();

    // Phase A2: gather. lanes = channels -> 128B coalesced per corner read.
    {
        int c = t & 63, half = t >> 6;
#pragma unroll 4
        for (int jj = 0; jj < 144; jj++) {
            int pair = jj*2 + half;
            int4 a = gA[pair]; float4 g = gW[pair];
            float v =      g.x * __ldg(in + a.x + c);
            v = fmaf(g.y, __ldg(in + a.y + c), v);
            v = fmaf(g.z, __ldg(in + a.z + c), v);
            v = fmaf(g.w, __ldg(in + a.w + c), v);
            int p = pair / 9; int i = pair - p*9;
            xoff[(c*9 + i)*36 + p] = v;
        }
    }
    __syncthreads();

    // Phase B: GEMM. thread = (og: 4 out-ch, pg: 4 pixels) -> 16 FMAs / k.
    {
        int og = t & 15, pg = t >> 4;
        float acc[16];
#pragma unroll
        for (int q = 0; q < 16; q++) acc[q] = 0.f;
        const float4* W4 = (const float4*)g_Wt + og;
        const float4* X4 = (const float4*)(xoff + pg*4);
#pragma unroll 4
        for (int k = 0; k < KK; k++) {
            float4 wv = __ldg(W4 + k*16);
            float4 xv = X4[k*9];
            acc[0]  = fmaf(wv.x, xv.x, acc[0]);
            acc[1]  = fmaf(wv.x, xv.y, acc[1]);
            acc[2]  = fmaf(wv.x, xv.z, acc[2]);
            acc[3]  = fmaf(wv.x, xv.w, acc[3]);
            acc[4]  = fmaf(wv.y, xv.x, acc[4]);
            acc[5]  = fmaf(wv.y, xv.y, acc[5]);
            acc[6]  = fmaf(wv.y, xv.z, acc[6]);
            acc[7]  = fmaf(wv.y, xv.w, acc[7]);
            acc[8]  = fmaf(wv.z, xv.x, acc[8]);
            acc[9]  = fmaf(wv.z, xv.y, acc[9]);
            acc[10] = fmaf(wv.z, xv.z, acc[10]);
            acc[11] = fmaf(wv.z, xv.w, acc[11]);
            acc[12] = fmaf(wv.w, xv.x, acc[12]);
            acc[13] = fmaf(wv.w, xv.y, acc[13]);
            acc[14] = fmaf(wv.w, xv.z, acc[14]);
            acc[15] = fmaf(wv.w, xv.w, acc[15]);
        }
#pragma unroll
        for (int pp = 0; pp < 4; pp++) {
            int pix = pix0 + pg*4 + pp;
            float4 o = make_float4(acc[pp], acc[4+pp], acc[8+pp], acc[12+pp]);
            *(float4*)(yout + pix*CH + og*4) = o;
        }
    }
}

// ---------------- BN stats: deterministic two-pass ----------------
__global__ __launch_bounds__(256) void k_bnstats(const float* __restrict__ y) {
    __shared__ float rs[256], rq[256];
    int t = threadIdx.x, blk = blockIdx.x;
    int c = t & 63, sub = t >> 6;
    float s = 0.f, q = 0.f;
    int base = blk * 392;
    for (int m = 0; m < 98; m++) {
        float v = y[(base + m*4 + sub)*CH + c];
        s += v;
        q = fmaf(v, v, q);
    }
    rs[t] = s; rq[t] = q;
    __syncthreads();
    if (t < 64) {
        s = rs[t] + rs[t+64] + rs[t+128] + rs[t+192];
        q = rq[t] + rq[t+64] + rq[t+128] + rq[t+192];
        g_sp[blk*64 + t] = s;
        g_qp[blk*64 + t] = q;
    }
}

__global__ void k_bnfinish(const float* __restrict__ gamma, const float* __restrict__ beta) {
    int c = threadIdx.x;
    float s = 0.f, q = 0.f;
    for (int i = 0; i < 256; i++) { s += g_sp[i*64 + c]; q += g_qp[i*64 + c]; }
    float inv = 1.f / (float)NPIX;
    float mean = s * inv;
    float var = fmaxf(q * inv - mean*mean, 0.f);
    float r = rsqrtf(var + 1e-5f);
    float a = gamma[c] * r;
    g_ab[c] = a;
    g_ab[64 + c] = beta[c] - mean * a;
}

// ---------------- BN apply + relu, NHWC -> NHWC (stage-1 output) ----------------
__global__ __launch_bounds__(256) void k_bnapply_nhwc(const float* __restrict__ y) {
    int v = blockIdx.x * 256 + threadIdx.x;   // one float4 each
    float4 t4 = ((const float4*)y)[v];
    int c = (v & 15) * 4;
    float4 r;
    r.x = fmaxf(fmaf(t4.x, g_ab[c+0], g_ab[64+c+0]), 0.f);
    r.y = fmaxf(fmaf(t4.y, g_ab[c+1], g_ab[64+c+1]), 0.f);
    r.z = fmaxf(fmaf(t4.z, g_ab[c+2], g_ab[64+c+2]), 0.f);
    r.w = fmaxf(fmaf(t4.w, g_ab[c+3], g_ab[64+c+3]), 0.f);
    ((float4*)g_y1n)[v] = r;
}

// ---------------- BN apply + relu + NHWC -> NCHW (final output) ----------------
__global__ __launch_bounds__(256) void k_bnapply_nchw(const float* __restrict__ y,
                                                      float* __restrict__ out) {
    __shared__ float tile[64*33];
    int t = threadIdx.x;
    int pix0 = blockIdx.x * 32;
    int b = pix0 / HW, hw0 = pix0 - b*HW;
    int c = t & 63, q = t >> 6;
    float a = g_ab[c], bb = g_ab[64 + c];
#pragma unroll
    for (int j = 0; j < 8; j++) {
        int p = q*8 + j;
        float v = y[(pix0 + p)*CH + c];
        tile[c*33 + p] = fmaxf(fmaf(v, a, bb), 0.f);
    }
    __syncthreads();
    int p2 = t & 31, cq = t >> 5;
#pragma unroll
    for (int j = 0; j < 8; j++) {
        int cc = cq*8 + j;
        out[(b*CH + cc)*HW + hw0 + p2] = tile[cc*33 + p2];
    }
}

// ---------------- launch ----------------
extern "C" void kernel_launch(void* const* d_in, const int* in_sizes, int n_in,
                              void* d_out, int out_size) {
    const float* x      = (const float*)d_in[0];
    const float* woff1  = (const float*)d_in[1];
    const float* boff1  = (const float*)d_in[2];
    const float* wconv1 = (const float*)d_in[3];
    const float* gamma1 = (const float*)d_in[4];
    const float* beta1  = (const float*)d_in[5];
    const float* woff2  = (const float*)d_in[6];
    const float* boff2  = (const float*)d_in[7];
    const float* wconv2 = (const float*)d_in[8];
    const float* gamma2 = (const float*)d_in[9];
    const float* beta2  = (const float*)d_in[10];
    float* out = (float*)d_out;

    float *p_xh, *p_y1n, *p_yraw;
    cudaGetSymbolAddress((void**)&p_xh,   g_xh);
    cudaGetSymbolAddress((void**)&p_y1n,  g_y1n);
    cudaGetSymbolAddress((void**)&p_yraw, g_yraw);

    cudaFuncSetAttribute(k_deform,  cudaFuncAttributeMaxDynamicSharedMemorySize, DEF_SMEM);
    cudaFuncSetAttribute(k_offconv, cudaFuncAttributeMaxDynamicSharedMemorySize, OFF_SMEM);

    // stage 1
    k_nchw2nhwc<<<dim3(HW/32, 2, BATCH), dim3(32, 8)>>>(x);
    k_prepwt<<<144, 256>>>(wconv1);
    k_offconv<<<dim3(4, HH, BATCH), 160, OFF_SMEM>>>(p_xh, woff1, boff1);
    k_deform<<<NPIX/32, 128, DEF_SMEM>>>(p_xh, p_yraw);
    k_bnstats<<<256, 256>>>(p_yraw);
    k_bnfinish<<<1, 64>>>(gamma1, beta1);
    k_bnapply_nhwc<<<NPIX*CH/4/256, 256>>>(p_yraw);

    // stage 2
    k_prepwt<<<144, 256>>>(wconv2);
    k_offconv<<<dim3(4, HH, BATCH), 160, OFF_SMEM>>>(p_y1n, woff2, boff2);
    k_deform<<<NPIX/32, 128, DEF_SMEM>>>(p_y1n, p_yraw);
    k_bnstats<<<256, 256>>>(p_yraw);
    k_bnfinish<<<1, 64>>>(gamma2, beta2);
    k_bnapply_nchw<<<NPIX/32, 256>>>(p_yraw, out);
}

// round 2
// speedup vs baseline: 3.1342x; 3.1342x over previous
#include <cuda_runtime.h>

#define BATCH 2
#define CH 64
#define HH 224
#define WW 224
#define HW (HH*WW)           // 50176
#define NPIX (BATCH*HW)      // 100352
#define NOFF 18
#define KK 576               // 64*9

typedef unsigned long long ull;

// ---------------- scratch (static device memory; no allocations) ----------------
__device__ float g_xh[NPIX*CH];      // NHWC input of current stage
__device__ float g_off[NPIX*NOFF];   // offsets NHWC
__device__ float g_xg[(size_t)NPIX*KK]; // gathered samples: xg[pix][i*64+c]
__device__ float g_yraw[NPIX*CH];    // pre-BN conv output NHWC
__device__ float g_y1n[NPIX*CH];     // stage-1 normalized output NHWC
__device__ float g_Wt[KK*CH];        // Wt[(i*64+c)*64+o] = w_conv[o][c*9+i]
__device__ float g_sp[256*CH];       // partial sums
__device__ float g_qp[256*CH];       // partial sumsq
__device__ float g_ab[2*CH];         // per-channel scale a, shift b

#define FMA2(acc, w, x) asm("fma.rn.f32x2 %0, %1, %2, %0;" : "+l"(acc) : "l"(w), "l"(x))

// ---------------- NCHW -> NHWC transpose ----------------
__global__ __launch_bounds__(256) void k_nchw2nhwc(const float* __restrict__ x) {
    __shared__ float tile[32][33];
    int b = blockIdx.z;
    int s0 = blockIdx.x * 32, c0 = blockIdx.y * 32;
    int tx = threadIdx.x, ty = threadIdx.y;
#pragma unroll
    for (int j = 0; j < 4; j++) {
        int c = c0 + ty + j*8;
        tile[ty + j*8][tx] = x[(b*CH + c)*HW + s0 + tx];
    }
    __syncthreads();
#pragma unroll
    for (int j = 0; j < 4; j++) {
        int s = s0 + ty + j*8;
        g_xh[(b*HW + s)*CH + c0 + tx] = tile[tx][ty + j*8];
    }
}

// ---------------- W prep: g_Wt[(i*64+c)*64 + o] = wconv[o][c*9+i] ----------------
__global__ void k_prepwt(const float* __restrict__ wconv) {
    int j = blockIdx.x * 256 + threadIdx.x;
    if (j < KK*CH) {
        int o = j & 63;
        int k = j >> 6;       // k = i*64 + c
        int i = k >> 6;
        int c = k & 63;
        g_Wt[j] = wconv[o*KK + c*9 + i];
    }
}

// ---------------- offset conv: 3x3, pad 1, 64->18 channels ----------------
#define OFF_SMEM ((10376 + 64*204) * 4)
__global__ __launch_bounds__(160) void k_offconv(const float* __restrict__ in,
                                                 const float* __restrict__ woff,
                                                 const float* __restrict__ boff) {
    extern __shared__ float sm[];
    float* Ws = sm;              // 10368 floats
    float* patch = sm + 10376;   // 64*204 floats
    int t = threadIdx.x;
    int w0 = blockIdx.x * 64, h = blockIdx.y, b = blockIdx.z;

    for (int j = t; j < NOFF*KK; j += 160) Ws[j] = woff[j];
    for (int j = t; j < 3*66*64; j += 160) {
        int c = j & 63; int r = j >> 6; int p = r % 66; int kx = r / 66;
        int hr = h - 1 + kx; int wc = w0 - 1 + p;
        float v = 0.f;
        if ((unsigned)hr < (unsigned)HH && (unsigned)wc < (unsigned)WW)
            v = in[((b*HH + hr)*WW + wc)*CH + c];
        patch[c*204 + kx*68 + p] = v;
    }
    __syncthreads();

    if (t < 144) {
        int og = t >> 4;
        int pl = t & 15;
        float acc0[4] = {0,0,0,0};
        float acc1[4] = {0,0,0,0};
        for (int c = 0; c < CH; c++) {
#pragma unroll
            for (int kx = 0; kx < 3; kx++) {
                const float* pr = patch + c*204 + kx*68 + pl*4;
                float4 f4 = *(const float4*)pr;
                float2 f2 = *(const float2*)(pr + 4);
                float pv[6] = {f4.x, f4.y, f4.z, f4.w, f2.x, f2.y};
                const float* wb0 = Ws + og*KK + c*9 + kx*3;
                const float* wb1 = Ws + (og+9)*KK + c*9 + kx*3;
#pragma unroll
                for (int ky = 0; ky < 3; ky++) {
                    float wa = wb0[ky], wb = wb1[ky];
#pragma unroll
                    for (int pp = 0; pp < 4; pp++) {
                        acc0[pp] = fmaf(wa, pv[ky+pp], acc0[pp]);
                        acc1[pp] = fmaf(wb, pv[ky+pp], acc1[pp]);
                    }
                }
            }
        }
        float bi0 = boff[og], bi1 = boff[og+9];
#pragma unroll
        for (int pp = 0; pp < 4; pp++) {
            int w = w0 + pl*4 + pp;
            if (w < WW) {
                int base = ((b*HH + h)*WW + w)*NOFF;
                g_off[base + og]     = acc0[pp] + bi0;
                g_off[base + og + 9] = acc1[pp] + bi1;
            }
        }
    }
}

// ---------------- gather: bilinear sample -> g_xg[pix][i*64+c] ----------------
__global__ __launch_bounds__(256) void k_gather(const float* __restrict__ in,
                                                float* __restrict__ xg) {
    __shared__ int4   gA[288];
    __shared__ float4 gW[288];
    int t = threadIdx.x;
    int pix0 = blockIdx.x * 32;
    int b = pix0 / HW; int hw = pix0 - b*HW;
    int h = hw / WW;  int w0 = hw - h*WW;

    for (int j = t; j < 288; j += 256) {
        int p = j / 9; int i = j - p*9;
        int pix = pix0 + p;
        float ox = g_off[pix*NOFF + i];
        float oy = g_off[pix*NOFF + 9 + i];
        float px = (float)(h + (i/3)) + ox;
        float py = (float)(w0 + p + (i%3)) + oy;
        float fx = floorf(px), fy = floorf(py);
        int x0 = (int)fx, y0 = (int)fy;
        int x1 = x0 + 1, y1 = y0 + 1;
        x0 = min(max(x0, 0), HH-1); x1 = min(max(x1, 0), HH-1);
        y0 = min(max(y0, 0), WW-1); y1 = min(max(y1, 0), WW-1);
        float pxc = fminf(fmaxf(px, 0.f), (float)(HH-1));
        float pyc = fminf(fmaxf(py, 0.f), (float)(WW-1));
        float wx0 = 1.f + (float)x0 - pxc;
        float wx1 = 1.f - (float)x1 + pxc;
        float wy0 = 1.f + (float)y0 - pyc;
        float wy1 = 1.f - (float)y1 + pyc;
        int base = b * HW;
        gA[j] = make_int4((base + x0*WW + y0)*CH, (base + x1*WW + y1)*CH,
                          (base + x0*WW + y1)*CH, (base + x1*WW + y0)*CH);
        gW[j] = make_float4(wx0*wy0, wx1*wy1, wx0*wy1, wx1*wy0);
    }
    __syncthreads();

    int c2 = (t & 31) * 2;
    int d0 = t >> 5;                 // warp id 0..7
#pragma unroll 4
    for (int it = 0; it < 36; it++) {
        int desc = d0 + it*8;
        int4 a = gA[desc]; float4 g = gW[desc];
        float2 v0 = *(const float2*)(in + a.x + c2);
        float2 v1 = *(const float2*)(in + a.y + c2);
        float2 v2 = *(const float2*)(in + a.z + c2);
        float2 v3 = *(const float2*)(in + a.w + c2);
        float2 r;
        r.x = fmaf(g.w, v3.x, fmaf(g.z, v2.x, fmaf(g.y, v1.x, g.x*v0.x)));
        r.y = fmaf(g.w, v3.y, fmaf(g.z, v2.y, fmaf(g.y, v1.y, g.x*v0.y)));
        int p = desc / 9; int i = desc - p*9;
        *(float2*)(xg + (size_t)(pix0 + p)*KK + i*64 + c2) = r;
    }
}

// ---------------- GEMM: yraw[pix][o] = sum_k Wt[k][o] * xg[pix][k] ----------------
// 128 pix x 64 och per block, 256 threads, k-chunks of 32, f32x2 packed math.
__global__ __launch_bounds__(256, 3) void k_gemm(const float* __restrict__ xg,
                                                 float* __restrict__ yout) {
    __shared__ float Xs[32*128];    // XOR-swizzled: [row k][phys col]
    __shared__ float Ws[32*64];
    int t = threadIdx.x;
    int pix0 = blockIdx.x * 128;
    int og = t & 15, pg = t >> 4;

    float4 xr[4]; float4 wr[2];

    // prefetch chunk 0
#pragma unroll
    for (int l = 0; l < 4; l++) {
        int idx = t + 256*l; int p = idx >> 3, kq = idx & 7;
        xr[l] = *(const float4*)(xg + (size_t)(pix0+p)*KK + kq*4);
    }
#pragma unroll
    for (int l = 0; l < 2; l++) {
        int idx = t + 256*l; int row = idx >> 4, q = idx & 15;
        wr[l] = *(const float4*)(g_Wt + row*64 + q*4);
    }

    ull acc[4][4];
#pragma unroll
    for (int a = 0; a < 4; a++)
#pragma unroll
        for (int q = 0; q < 4; q++) acc[a][q] = 0ull;

    for (int kc = 0; kc < 18; kc++) {
        __syncthreads();
        // store regs -> smem (X with XOR swizzle on 16B units, conflict-free)
#pragma unroll
        for (int l = 0; l < 4; l++) {
            int idx = t + 256*l; int p = idx >> 3, kq = idx & 7;
#pragma unroll
            for (int j = 0; j < 4; j++) {
                int row = kq*4 + j;
                Xs[row*128 + (((p>>2) ^ kq) << 2) + (p & 3)] = (&xr[l].x)[j];
            }
        }
#pragma unroll
        for (int l = 0; l < 2; l++) {
            int idx = t + 256*l; int row = idx >> 4, q = idx & 15;
            *(float4*)(Ws + row*64 + q*4) = wr[l];
        }
        __syncthreads();

        if (kc < 17) {
            int k0 = (kc+1)*32;
#pragma unroll
            for (int l = 0; l < 4; l++) {
                int idx = t + 256*l; int p = idx >> 3, kq = idx & 7;
                xr[l] = *(const float4*)(xg + (size_t)(pix0+p)*KK + k0 + kq*4);
            }
#pragma unroll
            for (int l = 0; l < 2; l++) {
                int idx = t + 256*l; int row = idx >> 4, q = idx & 15;
                wr[l] = *(const float4*)(g_Wt + (k0+row)*64 + q*4);
            }
        }

#pragma unroll
        for (int kk = 0; kk < 32; kk++) {
            float4 wv = *(const float4*)(Ws + kk*64 + og*4);
            int s = kk >> 2;
            const float* xrow = Xs + kk*128;
            int uA = (((pg*2)   ^ s) << 2);
            int uB = (((pg*2+1) ^ s) << 2);
            ull x0 = *(const ull*)(xrow + uA);
            ull x1 = *(const ull*)(xrow + uA + 2);
            ull x2 = *(const ull*)(xrow + uB);
            ull x3 = *(const ull*)(xrow + uB + 2);
#pragma unroll
            for (int a = 0; a < 4; a++) {
                float wa = (&wv.x)[a];
                ull w2;
                asm("mov.b64 %0, {%1, %1};" : "=l"(w2) : "f"(wa));
                FMA2(acc[a][0], w2, x0);
                FMA2(acc[a][1], w2, x1);
                FMA2(acc[a][2], w2, x2);
                FMA2(acc[a][3], w2, x3);
            }
        }
    }

    // epilogue: unpack pairs, write NHWC
#pragma unroll
    for (int q = 0; q < 4; q++) {
        float lo[4], hi[4];
#pragma unroll
        for (int a = 0; a < 4; a++) {
            asm("mov.b64 {%0, %1}, %2;" : "=f"(lo[a]), "=f"(hi[a]) : "l"(acc[a][q]));
        }
        int p = pix0 + pg*8 + 2*q;
        *(float4*)(yout + (size_t)p*CH + og*4)     = make_float4(lo[0], lo[1], lo[2], lo[3]);
        *(float4*)(yout + (size_t)(p+1)*CH + og*4) = make_float4(hi[0], hi[1], hi[2], hi[3]);
    }
}

// ---------------- BN stats: deterministic two-pass ----------------
__global__ __launch_bounds__(256) void k_bnstats(const float* __restrict__ y) {
    __shared__ float rs[256], rq[256];
    int t = threadIdx.x, blk = blockIdx.x;
    int c = t & 63, sub = t >> 6;
    float s = 0.f, q = 0.f;
    int base = blk * 392;
    for (int m = 0; m < 98; m++) {
        float v = y[(base + m*4 + sub)*CH + c];
        s += v;
        q = fmaf(v, v, q);
    }
    rs[t] = s; rq[t] = q;
    __syncthreads();
    if (t < 64) {
        s = rs[t] + rs[t+64] + rs[t+128] + rs[t+192];
        q = rq[t] + rq[t+64] + rq[t+128] + rq[t+192];
        g_sp[blk*64 + t] = s;
        g_qp[blk*64 + t] = q;
    }
}

__global__ void k_bnfinish(const float* __restrict__ gamma, const float* __restrict__ beta) {
    int c = threadIdx.x;
    float s = 0.f, q = 0.f;
    for (int i = 0; i < 256; i++) { s += g_sp[i*64 + c]; q += g_qp[i*64 + c]; }
    float inv = 1.f / (float)NPIX;
    float mean = s * inv;
    float var = fmaxf(q * inv - mean*mean, 0.f);
    float r = rsqrtf(var + 1e-5f);
    float a = gamma[c] * r;
    g_ab[c] = a;
    g_ab[64 + c] = beta[c] - mean * a;
}

// ---------------- BN apply + relu, NHWC -> NHWC (stage-1 output) ----------------
__global__ __launch_bounds__(256) void k_bnapply_nhwc(const float* __restrict__ y) {
    int v = blockIdx.x * 256 + threadIdx.x;
    float4 t4 = ((const float4*)y)[v];
    int c = (v & 15) * 4;
    float4 r;
    r.x = fmaxf(fmaf(t4.x, g_ab[c+0], g_ab[64+c+0]), 0.f);
    r.y = fmaxf(fmaf(t4.y, g_ab[c+1], g_ab[64+c+1]), 0.f);
    r.z = fmaxf(fmaf(t4.z, g_ab[c+2], g_ab[64+c+2]), 0.f);
    r.w = fmaxf(fmaf(t4.w, g_ab[c+3], g_ab[64+c+3]), 0.f);
    ((float4*)g_y1n)[v] = r;
}

// ---------------- BN apply + relu + NHWC -> NCHW (final output) ----------------
__global__ __launch_bounds__(256) void k_bnapply_nchw(const float* __restrict__ y,
                                                      float* __restrict__ out) {
    __shared__ float tile[64*33];
    int t = threadIdx.x;
    int pix0 = blockIdx.x * 32;
    int b = pix0 / HW, hw0 = pix0 - b*HW;
    int c = t & 63, q = t >> 6;
    float a = g_ab[c], bb = g_ab[64 + c];
#pragma unroll
    for (int j = 0; j < 8; j++) {
        int p = q*8 + j;
        float v = y[(pix0 + p)*CH + c];
        tile[c*33 + p] = fmaxf(fmaf(v, a, bb), 0.f);
    }
    __syncthreads();
    int p2 = t & 31, cq = t >> 5;
#pragma unroll
    for (int j = 0; j < 8; j++) {
        int cc = cq*8 + j;
        out[(b*CH + cc)*HW + hw0 + p2] = tile[cc*33 + p2];
    }
}

// ---------------- launch ----------------
extern "C" void kernel_launch(void* const* d_in, const int* in_sizes, int n_in,
                              void* d_out, int out_size) {
    const float* x      = (const float*)d_in[0];
    const float* woff1  = (const float*)d_in[1];
    const float* boff1  = (const float*)d_in[2];
    const float* wconv1 = (const float*)d_in[3];
    const float* gamma1 = (const float*)d_in[4];
    const float* beta1  = (const float*)d_in[5];
    const float* woff2  = (const float*)d_in[6];
    const float* boff2  = (const float*)d_in[7];
    const float* wconv2 = (const float*)d_in[8];
    const float* gamma2 = (const float*)d_in[9];
    const float* beta2  = (const float*)d_in[10];
    float* out = (float*)d_out;

    float *p_xh, *p_y1n, *p_yraw, *p_xg;
    cudaGetSymbolAddress((void**)&p_xh,   g_xh);
    cudaGetSymbolAddress((void**)&p_y1n,  g_y1n);
    cudaGetSymbolAddress((void**)&p_yraw, g_yraw);
    cudaGetSymbolAddress((void**)&p_xg,   g_xg);

    cudaFuncSetAttribute(k_offconv, cudaFuncAttributeMaxDynamicSharedMemorySize, OFF_SMEM);

    // stage 1
    k_nchw2nhwc<<<dim3(HW/32, 2, BATCH), dim3(32, 8)>>>(x);
    k_prepwt<<<144, 256>>>(wconv1);
    k_offconv<<<dim3(4, HH, BATCH), 160, OFF_SMEM>>>(p_xh, woff1, boff1);
    k_gather<<<NPIX/32, 256>>>(p_xh, p_xg);
    k_gemm<<<NPIX/128, 256>>>(p_xg, p_yraw);
    k_bnstats<<<256, 256>>>(p_yraw);
    k_bnfinish<<<1, 64>>>(gamma1, beta1);
    k_bnapply_nhwc<<<NPIX*CH/4/256, 256>>>(p_yraw);

    // stage 2
    k_prepwt<<<144, 256>>>(wconv2);
    k_offconv<<<dim3(4, HH, BATCH), 160, OFF_SMEM>>>(p_y1n, woff2, boff2);
    k_gather<<<NPIX/32, 256>>>(p_y1n, p_xg);
    k_gemm<<<NPIX/128, 256>>>(p_xg, p_yraw);
    k_bnstats<<<256, 256>>>(p_yraw);
    k_bnfinish<<<1, 64>>>(gamma2, beta2);
    k_bnapply_nchw<<<NPIX/32, 256>>>(p_yraw, out);
}